// round 1
// baseline (speedup 1.0000x reference)
#include <cuda_runtime.h>
#include <math.h>

#define Bz   128
#define Hh   512
#define G4   2048      // 4*H
#define Tt   256
#define INZ  64
#define OUTL 512

// ---------------- device scratch (no cudaMalloc allowed) ----------------
__device__ float g_xpe[Tt * Bz * G4];   // encoder input projections [t][b][4H]
__device__ float g_xpd[Tt * Bz * G4];   // decoder input projections [t][b][4H]
__device__ float g_hse[Tt * Bz * Hh];   // encoder hidden states [t][b][H]
__device__ float g_hsd[Tt * Bz * Hh];   // decoder hidden states [t][b][H]
__device__ float g_hA[Bz * Hh];
__device__ float g_hB[Bz * Hh];
__device__ float g_cE[Bz * Hh];
__device__ float g_h2A[Bz * Hh];
__device__ float g_h2B[Bz * Hh];
__device__ float g_cD[Bz * Hh];
__device__ float g_fcp[Tt * Bz * OUTL]; // FC partials [t][b][o]

// ---------------- init ----------------
__global__ void init_kernel(const float* __restrict__ h0e, const float* __restrict__ c0e,
                            const float* __restrict__ h0d, const float* __restrict__ c0d) {
    int i = blockIdx.x * blockDim.x + threadIdx.x;
    if (i < Bz * Hh) {
        g_hA[i]  = h0e[i];
        g_cE[i]  = c0e[i];
        g_h2A[i] = h0d[i];
        g_cD[i]  = c0d[i];
    }
}

// ---------------- input projection GEMM ----------------
// out[m*2048+n] = sum_k A[m][k] * W[n][k] + b0[n] + b1[n]
// MODE 0: A gathered from x (B, 64, T): A[m][k] = x[b*64*256 + k*256 + t], m = t*128+b, K=64
// MODE 1: A contiguous rows of hs_e: A[m][k] = hs[m*512+k], K=512
// BM=BN=128, BK=8, 256 threads, 8x8 micro-tile, register prefetch.
template <int MODE>
__global__ void __launch_bounds__(256)
inproj_gemm(const float* __restrict__ A_or_x, const float* __restrict__ W,
            const float* __restrict__ b0v, const float* __restrict__ b1v,
            float* __restrict__ out, int K) {
    __shared__ __align__(16) float As[8][128];
    __shared__ __align__(16) float Bs[8][128];

    const int m0  = blockIdx.y * 128;
    const int n0  = blockIdx.x * 128;
    const int tid = threadIdx.x;
    const int txx = tid & 15;
    const int tyy = tid >> 4;
    const int lrow = tid >> 1;        // 0..127
    const int lkq  = (tid & 1) * 4;   // 0 or 4

    float acc[8][8];
#pragma unroll
    for (int i = 0; i < 8; i++)
#pragma unroll
        for (int j = 0; j < 8; j++) acc[i][j] = 0.f;

    // prefetch registers
    float4 aPf, bPf;
    float  aPfS[4];

    // first chunk load
    {
        if (MODE == 1) {
            aPf = *reinterpret_cast<const float4*>(&A_or_x[(size_t)(m0 + lrow) * K + lkq]);
        } else {
            int m = m0 + lrow;
            int tt = m >> 7, b = m & 127;
#pragma unroll
            for (int i = 0; i < 4; i++)
                aPfS[i] = A_or_x[(size_t)b * (INZ * Tt) + (size_t)(lkq + i) * Tt + tt];
        }
        bPf = *reinterpret_cast<const float4*>(&W[(size_t)(n0 + lrow) * K + lkq]);
    }

    for (int k0 = 0; k0 < K; k0 += 8) {
        // commit prefetched to smem
        if (MODE == 1) {
            As[lkq + 0][lrow] = aPf.x; As[lkq + 1][lrow] = aPf.y;
            As[lkq + 2][lrow] = aPf.z; As[lkq + 3][lrow] = aPf.w;
        } else {
#pragma unroll
            for (int i = 0; i < 4; i++) As[lkq + i][lrow] = aPfS[i];
        }
        Bs[lkq + 0][lrow] = bPf.x; Bs[lkq + 1][lrow] = bPf.y;
        Bs[lkq + 2][lrow] = bPf.z; Bs[lkq + 3][lrow] = bPf.w;
        __syncthreads();

        // issue next chunk loads (hidden under compute)
        int kn = k0 + 8;
        if (kn < K) {
            if (MODE == 1) {
                aPf = *reinterpret_cast<const float4*>(&A_or_x[(size_t)(m0 + lrow) * K + kn + lkq]);
            } else {
                int m = m0 + lrow;
                int tt = m >> 7, b = m & 127;
#pragma unroll
                for (int i = 0; i < 4; i++)
                    aPfS[i] = A_or_x[(size_t)b * (INZ * Tt) + (size_t)(kn + lkq + i) * Tt + tt];
            }
            bPf = *reinterpret_cast<const float4*>(&W[(size_t)(n0 + lrow) * K + kn + lkq]);
        }

#pragma unroll
        for (int kk = 0; kk < 8; kk++) {
            float a[8], bb[8];
            *reinterpret_cast<float4*>(&a[0]) = *reinterpret_cast<const float4*>(&As[kk][tyy * 8]);
            *reinterpret_cast<float4*>(&a[4]) = *reinterpret_cast<const float4*>(&As[kk][tyy * 8 + 4]);
            *reinterpret_cast<float4*>(&bb[0]) = *reinterpret_cast<const float4*>(&Bs[kk][txx * 8]);
            *reinterpret_cast<float4*>(&bb[4]) = *reinterpret_cast<const float4*>(&Bs[kk][txx * 8 + 4]);
#pragma unroll
            for (int i = 0; i < 8; i++)
#pragma unroll
                for (int j = 0; j < 8; j++)
                    acc[i][j] = fmaf(a[i], bb[j], acc[i][j]);
        }
        __syncthreads();
    }

#pragma unroll
    for (int i = 0; i < 8; i++) {
        int m = m0 + tyy * 8 + i;
#pragma unroll
        for (int j = 0; j < 8; j++) {
            int n = n0 + txx * 8 + j;
            out[(size_t)m * G4 + n] = acc[i][j] + b0v[n] + b1v[n];
        }
    }
}

// ---------------- fused LSTM step ----------------
// grid (4, 32), 128 threads. Block: b-tile 32, hidx-tile 16, all 4 gates.
// gates[b][q*512+hidx] = xp[b][q*512+hidx] + sum_k h_prev[b][k] * Whh[q*512+hidx][k]
template <bool WRITE_ENC>
__global__ void __launch_bounds__(128)
lstm_step(const float* __restrict__ xp,       // g_xp? + t*B*2048
          const float* __restrict__ whh,      // [2048][512]
          const float* __restrict__ h_prev,   // [B][512]
          float* __restrict__ h_next,
          float* __restrict__ c_state,
          float* __restrict__ hs_out,         // g_hs? + t*B*512
          float* __restrict__ enc_out,        // d_out (encoded region)
          int t) {
    const int b0 = blockIdx.x * 32;
    const int h0 = blockIdx.y * 16;
    const int tx = threadIdx.x & 15;   // hidx within tile
    const int tb = threadIdx.x >> 4;   // 0..7 -> group of 4 b
    const int hidx = h0 + tx;

    __shared__ __align__(16) float hs_s[16][32];
    __shared__ __align__(16) float ws_s[16][64];   // [k][hh*4 + q]

    float acc[4][4];
#pragma unroll
    for (int q = 0; q < 4; q++)
#pragma unroll
        for (int r = 0; r < 4; r++) acc[q][r] = 0.f;

    // prefetch state
    const int lbb = threadIdx.x & 31;
    const int lkq = threadIdx.x >> 5;          // 0..3
    float4 hPf, wPf0, wPf1;
    int wrow0, wkq0, wrow1, wkq1;
    {
        hPf = *reinterpret_cast<const float4*>(&h_prev[(b0 + lbb) * Hh + lkq * 4]);
        int f0 = threadIdx.x * 2, f1 = f0 + 1;
        wrow0 = f0 >> 2; wkq0 = f0 & 3;
        wrow1 = f1 >> 2; wkq1 = f1 & 3;
        int q0 = wrow0 >> 4, hh0 = wrow0 & 15;
        int q1 = wrow1 >> 4, hh1 = wrow1 & 15;
        wPf0 = *reinterpret_cast<const float4*>(&whh[(size_t)(q0 * Hh + h0 + hh0) * Hh + wkq0 * 4]);
        wPf1 = *reinterpret_cast<const float4*>(&whh[(size_t)(q1 * Hh + h0 + hh1) * Hh + wkq1 * 4]);
    }

    for (int k0 = 0; k0 < Hh; k0 += 16) {
        // commit prefetch
        hs_s[lkq * 4 + 0][lbb] = hPf.x; hs_s[lkq * 4 + 1][lbb] = hPf.y;
        hs_s[lkq * 4 + 2][lbb] = hPf.z; hs_s[lkq * 4 + 3][lbb] = hPf.w;
        {
            int q0 = wrow0 >> 4, hh0 = wrow0 & 15;
            int q1 = wrow1 >> 4, hh1 = wrow1 & 15;
            ws_s[wkq0 * 4 + 0][hh0 * 4 + q0] = wPf0.x;
            ws_s[wkq0 * 4 + 1][hh0 * 4 + q0] = wPf0.y;
            ws_s[wkq0 * 4 + 2][hh0 * 4 + q0] = wPf0.z;
            ws_s[wkq0 * 4 + 3][hh0 * 4 + q0] = wPf0.w;
            ws_s[wkq1 * 4 + 0][hh1 * 4 + q1] = wPf1.x;
            ws_s[wkq1 * 4 + 1][hh1 * 4 + q1] = wPf1.y;
            ws_s[wkq1 * 4 + 2][hh1 * 4 + q1] = wPf1.z;
            ws_s[wkq1 * 4 + 3][hh1 * 4 + q1] = wPf1.w;
        }
        __syncthreads();

        int kn = k0 + 16;
        if (kn < Hh) {
            hPf = *reinterpret_cast<const float4*>(&h_prev[(b0 + lbb) * Hh + kn + lkq * 4]);
            int q0 = wrow0 >> 4, hh0 = wrow0 & 15;
            int q1 = wrow1 >> 4, hh1 = wrow1 & 15;
            wPf0 = *reinterpret_cast<const float4*>(&whh[(size_t)(q0 * Hh + h0 + hh0) * Hh + kn + wkq0 * 4]);
            wPf1 = *reinterpret_cast<const float4*>(&whh[(size_t)(q1 * Hh + h0 + hh1) * Hh + kn + wkq1 * 4]);
        }

#pragma unroll
        for (int k = 0; k < 16; k++) {
            float4 hv = *reinterpret_cast<const float4*>(&hs_s[k][tb * 4]);
            float4 wv = *reinterpret_cast<const float4*>(&ws_s[k][tx * 4]);
            float hr[4] = {hv.x, hv.y, hv.z, hv.w};
            float wq[4] = {wv.x, wv.y, wv.z, wv.w};
#pragma unroll
            for (int q = 0; q < 4; q++)
#pragma unroll
                for (int r = 0; r < 4; r++)
                    acc[q][r] = fmaf(hr[r], wq[q], acc[q][r]);
        }
        __syncthreads();
    }

    // pointwise epilogue (gate order i, f, g, o)
#pragma unroll
    for (int r = 0; r < 4; r++) {
        int b = b0 + tb * 4 + r;
        const float* xpb = xp + (size_t)b * G4;
        float gi = acc[0][r] + xpb[0 * Hh + hidx];
        float gf = acc[1][r] + xpb[1 * Hh + hidx];
        float gg = acc[2][r] + xpb[2 * Hh + hidx];
        float go = acc[3][r] + xpb[3 * Hh + hidx];
        float i_ = 1.f / (1.f + expf(-gi));
        float f_ = 1.f / (1.f + expf(-gf));
        float o_ = 1.f / (1.f + expf(-go));
        float g_ = tanhf(gg);
        int idx = b * Hh + hidx;
        float c_new = f_ * c_state[idx] + i_ * g_;
        float h = o_ * tanhf(c_new);
        c_state[idx] = c_new;
        h_next[idx]  = h;
        hs_out[idx]  = h;
        if (WRITE_ENC)
            enc_out[(size_t)b * (Hh * Tt) + (size_t)hidx * Tt + t] = h;
    }
}

// ---------------- FC: per-t partial GEMM (k-split over t) ----------------
// partial[t][b][o] = sum_h hsd[t][b][h] * Wfc[o][h*256 + t]
// grid (4, 256): x = o-tile (128), y = t. 256 threads, 8x8 micro.
__global__ void __launch_bounds__(256)
fc_partial(const float* __restrict__ hsd, const float* __restrict__ Wfc) {
    const int t  = blockIdx.y;
    const int o0 = blockIdx.x * 128;
    const int tid = threadIdx.x;
    const int txx = tid & 15;
    const int tyy = tid >> 4;
    const int lrow = tid >> 1;
    const int lkq  = (tid & 1) * 4;

    __shared__ __align__(16) float As[8][128];   // [h][b]
    __shared__ __align__(16) float Bs[8][128];   // [h][o]

    float acc[8][8];
#pragma unroll
    for (int i = 0; i < 8; i++)
#pragma unroll
        for (int j = 0; j < 8; j++) acc[i][j] = 0.f;

    const float* Abase = hsd + (size_t)t * (Bz * Hh);

    for (int h0 = 0; h0 < Hh; h0 += 8) {
        {
            float4 v = *reinterpret_cast<const float4*>(&Abase[(size_t)lrow * Hh + h0 + lkq]);
            As[lkq + 0][lrow] = v.x; As[lkq + 1][lrow] = v.y;
            As[lkq + 2][lrow] = v.z; As[lkq + 3][lrow] = v.w;
        }
#pragma unroll
        for (int i = 0; i < 4; i++)
            Bs[lkq + i][lrow] = Wfc[(size_t)(o0 + lrow) * (Hh * Tt) + (size_t)(h0 + lkq + i) * Tt + t];
        __syncthreads();
#pragma unroll
        for (int kk = 0; kk < 8; kk++) {
            float a[8], bb[8];
            *reinterpret_cast<float4*>(&a[0]) = *reinterpret_cast<const float4*>(&As[kk][tyy * 8]);
            *reinterpret_cast<float4*>(&a[4]) = *reinterpret_cast<const float4*>(&As[kk][tyy * 8 + 4]);
            *reinterpret_cast<float4*>(&bb[0]) = *reinterpret_cast<const float4*>(&Bs[kk][txx * 8]);
            *reinterpret_cast<float4*>(&bb[4]) = *reinterpret_cast<const float4*>(&Bs[kk][txx * 8 + 4]);
#pragma unroll
            for (int i = 0; i < 8; i++)
#pragma unroll
                for (int j = 0; j < 8; j++)
                    acc[i][j] = fmaf(a[i], bb[j], acc[i][j]);
        }
        __syncthreads();
    }

    float* part = g_fcp + (size_t)t * (Bz * OUTL);
#pragma unroll
    for (int i = 0; i < 8; i++) {
        int b = tyy * 8 + i;
#pragma unroll
        for (int j = 0; j < 8; j++) {
            int o = o0 + txx * 8 + j;
            part[(size_t)b * OUTL + o] = acc[i][j];
        }
    }
}

__global__ void fc_reduce(const float* __restrict__ bfc, float* __restrict__ decoded) {
    int i = blockIdx.x * blockDim.x + threadIdx.x;   // 65536 outputs
    if (i >= Bz * OUTL) return;
    float s = bfc[i & (OUTL - 1)];
    for (int t = 0; t < Tt; t++) s += g_fcp[(size_t)t * (Bz * OUTL) + i];
    decoded[i] = s;
}

// ---------------- launch ----------------
extern "C" void kernel_launch(void* const* d_in, const int* in_sizes, int n_in,
                              void* d_out, int out_size) {
    const float* x     = (const float*)d_in[0];
    const float* h0e   = (const float*)d_in[1];
    const float* c0e   = (const float*)d_in[2];
    const float* Wih_e = (const float*)d_in[3];
    const float* Whh_e = (const float*)d_in[4];
    const float* bih_e = (const float*)d_in[5];
    const float* bhh_e = (const float*)d_in[6];
    const float* h0d   = (const float*)d_in[7];
    const float* c0d   = (const float*)d_in[8];
    const float* Wih_d = (const float*)d_in[9];
    const float* Whh_d = (const float*)d_in[10];
    const float* bih_d = (const float*)d_in[11];
    const float* bhh_d = (const float*)d_in[12];
    const float* Wfc   = (const float*)d_in[13];
    const float* bfc   = (const float*)d_in[14];

    float* out = (float*)d_out;
    float* enc_out = out;                              // (B, H, T)
    float* decoded = out + (size_t)Bz * Hh * Tt;       // (B, OUT_LEN)

    float *xpe, *xpd, *hse, *hsd, *hA, *hB, *cE, *h2A, *h2B, *cD;
    cudaGetSymbolAddress((void**)&xpe, g_xpe);
    cudaGetSymbolAddress((void**)&xpd, g_xpd);
    cudaGetSymbolAddress((void**)&hse, g_hse);
    cudaGetSymbolAddress((void**)&hsd, g_hsd);
    cudaGetSymbolAddress((void**)&hA,  g_hA);
    cudaGetSymbolAddress((void**)&hB,  g_hB);
    cudaGetSymbolAddress((void**)&cE,  g_cE);
    cudaGetSymbolAddress((void**)&h2A, g_h2A);
    cudaGetSymbolAddress((void**)&h2B, g_h2B);
    cudaGetSymbolAddress((void**)&cD,  g_cD);

    init_kernel<<<(Bz * Hh + 255) / 256, 256>>>(h0e, c0e, h0d, c0d);

    // encoder input projections: all t at once
    inproj_gemm<0><<<dim3(16, 256), 256>>>(x, Wih_e, bih_e, bhh_e, xpe, INZ);

    // encoder recurrence
    for (int t = 0; t < Tt; t++) {
        const float* hp = (t & 1) ? hB : hA;
        float*       hn = (t & 1) ? hA : hB;
        lstm_step<true><<<dim3(4, 32), 128>>>(
            xpe + (size_t)t * Bz * G4, Whh_e, hp, hn, cE,
            hse + (size_t)t * Bz * Hh, enc_out, t);
    }

    // decoder input projections over hs_e
    inproj_gemm<1><<<dim3(16, 256), 256>>>(hse, Wih_d, bih_d, bhh_d, xpd, Hh);

    // decoder recurrence
    for (int t = 0; t < Tt; t++) {
        const float* hp = (t & 1) ? h2B : h2A;
        float*       hn = (t & 1) ? h2A : h2B;
        lstm_step<false><<<dim3(4, 32), 128>>>(
            xpd + (size_t)t * Bz * G4, Whh_d, hp, hn, cD,
            hsd + (size_t)t * Bz * Hh, nullptr, t);
    }

    // final FC
    fc_partial<<<dim3(4, Tt), 256>>>(hsd, Wfc);
    fc_reduce<<<(Bz * OUTL + 255) / 256, 256>>>(bfc, decoded);
}

// round 2
// speedup vs baseline: 1.2336x; 1.2336x over previous
#include <cuda_runtime.h>
#include <math.h>

#define Bz   128
#define Hh   512
#define G4   2048
#define Tt   256
#define INZ  64
#define OUTL 512
#define NBLK 128

typedef unsigned long long u64;

// ---------------- device scratch ----------------
__device__ float g_xpe[(size_t)Tt * Bz * G4];   // [t][b][4H]
__device__ float g_xpd[(size_t)Tt * Bz * G4];
__device__ float g_hse[(size_t)Tt * Hh * Bz];   // [t][h][b] (transposed)
__device__ float g_hsd[(size_t)Tt * Hh * Bz];
__device__ float g_hA[Hh * Bz];                 // h ping/pong, layout [k][b]
__device__ float g_hB[Hh * Bz];
__device__ float g_h2A[Hh * Bz];
__device__ float g_h2B[Hh * Bz];
__device__ float g_fcp[(size_t)Tt * Bz * OUTL];
__device__ unsigned g_barCnt[2];
__device__ unsigned g_barPhase[2];

// ---------------- f32x2 helpers ----------------
__device__ __forceinline__ u64 pack2(float lo, float hi) {
    u64 r; asm("mov.b64 %0,{%1,%2};" : "=l"(r) : "f"(lo), "f"(hi)); return r;
}
__device__ __forceinline__ void unpack2(u64 v, float& lo, float& hi) {
    asm("mov.b64 {%0,%1},%2;" : "=f"(lo), "=f"(hi) : "l"(v));
}
__device__ __forceinline__ u64 fma2(u64 a, u64 b, u64 c) {
    u64 d; asm("fma.rn.f32x2 %0,%1,%2,%3;" : "=l"(d) : "l"(a), "l"(b), "l"(c)); return d;
}
__device__ __forceinline__ u64 add2(u64 a, u64 b) {
    u64 d; asm("add.rn.f32x2 %0,%1,%2;" : "=l"(d) : "l"(a), "l"(b)); return d;
}
__device__ __forceinline__ float fsig(float x) { return __fdividef(1.f, 1.f + __expf(-x)); }
__device__ __forceinline__ float ftanh_(float x) { return 2.f * fsig(2.f * x) - 1.f; }

// ---------------- init ----------------
__global__ void init_all(const float* __restrict__ h0e, const float* __restrict__ h0d) {
    int i = blockIdx.x * blockDim.x + threadIdx.x;
    if (i < Hh * Bz) {
        int k = i >> 7, b = i & 127;
        g_hA[i]  = h0e[b * Hh + k];   // transpose into [k][b]
        g_h2A[i] = h0d[b * Hh + k];
    }
    if (i < 2) { g_barCnt[i] = 0u; g_barPhase[i] = 0u; }
}

// ---------------- input projection GEMM ----------------
// out[(t*128+b)*2048 + n] = sum_k A[m][k]*W[n][k] + b0[n] + b1[n]
// MODE 0: A[m][k] = x[b][k][t],  x is (B, 64, T), K=64
// MODE 1: A[m][k] = hse_t[t][k][b] ([t][512][128] layout), K=512
template <int MODE>
__global__ void __launch_bounds__(256)
inproj_gemm(const float* __restrict__ A_or_x, const float* __restrict__ W,
            const float* __restrict__ b0v, const float* __restrict__ b1v,
            float* __restrict__ out, int K) {
    __shared__ __align__(16) float As[8][128];
    __shared__ __align__(16) float Bs[8][128];

    const int m0  = blockIdx.y * 128;
    const int n0  = blockIdx.x * 128;
    const int tid = threadIdx.x;
    const int txx = tid & 15;
    const int tyy = tid >> 4;
    const int lrow = tid >> 1;
    const int lkq  = (tid & 1) * 4;
    const int arow = tid >> 5;          // MODE1: k-row 0..7
    const int acol = (tid & 31) * 4;    // MODE1: b-col

    float acc[8][8];
#pragma unroll
    for (int i = 0; i < 8; i++)
#pragma unroll
        for (int j = 0; j < 8; j++) acc[i][j] = 0.f;

    float4 aPf, bPf;
    float  aPfS[4];

    if (MODE == 1) {
        aPf = *reinterpret_cast<const float4*>(
            &A_or_x[(size_t)blockIdx.y * Hh * Bz + (size_t)arow * Bz + acol]);
    } else {
        int m = m0 + lrow;
        int tt = m >> 7, b = m & 127;
#pragma unroll
        for (int i = 0; i < 4; i++)
            aPfS[i] = A_or_x[(size_t)b * (INZ * Tt) + (size_t)(lkq + i) * Tt + tt];
    }
    bPf = *reinterpret_cast<const float4*>(&W[(size_t)(n0 + lrow) * K + lkq]);

    for (int k0 = 0; k0 < K; k0 += 8) {
        if (MODE == 1) {
            *reinterpret_cast<float4*>(&As[arow][acol]) = aPf;
        } else {
#pragma unroll
            for (int i = 0; i < 4; i++) As[lkq + i][lrow] = aPfS[i];
        }
        Bs[lkq + 0][lrow] = bPf.x; Bs[lkq + 1][lrow] = bPf.y;
        Bs[lkq + 2][lrow] = bPf.z; Bs[lkq + 3][lrow] = bPf.w;
        __syncthreads();

        int kn = k0 + 8;
        if (kn < K) {
            if (MODE == 1) {
                aPf = *reinterpret_cast<const float4*>(
                    &A_or_x[(size_t)blockIdx.y * Hh * Bz + (size_t)(kn + arow) * Bz + acol]);
            } else {
                int m = m0 + lrow;
                int tt = m >> 7, b = m & 127;
#pragma unroll
                for (int i = 0; i < 4; i++)
                    aPfS[i] = A_or_x[(size_t)b * (INZ * Tt) + (size_t)(kn + lkq + i) * Tt + tt];
            }
            bPf = *reinterpret_cast<const float4*>(&W[(size_t)(n0 + lrow) * K + kn + lkq]);
        }

#pragma unroll
        for (int kk = 0; kk < 8; kk++) {
            float a[8], bb[8];
            *reinterpret_cast<float4*>(&a[0]) = *reinterpret_cast<const float4*>(&As[kk][tyy * 8]);
            *reinterpret_cast<float4*>(&a[4]) = *reinterpret_cast<const float4*>(&As[kk][tyy * 8 + 4]);
            *reinterpret_cast<float4*>(&bb[0]) = *reinterpret_cast<const float4*>(&Bs[kk][txx * 8]);
            *reinterpret_cast<float4*>(&bb[4]) = *reinterpret_cast<const float4*>(&Bs[kk][txx * 8 + 4]);
#pragma unroll
            for (int i = 0; i < 8; i++)
#pragma unroll
                for (int j = 0; j < 8; j++)
                    acc[i][j] = fmaf(a[i], bb[j], acc[i][j]);
        }
        __syncthreads();
    }

#pragma unroll
    for (int i = 0; i < 8; i++) {
        int m = m0 + tyy * 8 + i;
#pragma unroll
        for (int j = 0; j < 8; j++) {
            int n = n0 + txx * 8 + j;
            out[(size_t)m * G4 + n] = acc[i][j] + b0v[n] + b1v[n];
        }
    }
}

// ---------------- persistent LSTM ----------------
// 128 blocks x 256 threads. Block owns hidx = bid*4..bid*4+3 (x 4 gates = 16 weight rows,
// kept in SMEM pre-splatted as f32x2 for the whole sequence). c-state lives in SMEM.
// Grid barrier between steps. h layout [k][b], ping-pong buffers.
__global__ void __launch_bounds__(256, 1)
lstm_persistent(const float* __restrict__ xp_all,   // [t][b][2048]
                const float* __restrict__ whh,      // [2048][512]
                const float* __restrict__ c0,       // [b][512]
                float* __restrict__ hbuf0,          // [512][128]
                float* __restrict__ hbuf1,
                float* __restrict__ hs_t,           // [t][512][128]
                int barSel) {
    extern __shared__ char sm_[];
    u64*   ws2 = (u64*)sm_;                          // [512][16]  (w,w) splats, 64KB
    float* hb  = (float*)(sm_ + 65536);              // [2][64][128] 64KB
    u64*   red = (u64*)(sm_ + 131072);               // [128][8] 8KB
    float* xs  = (float*)(sm_ + 131072 + 8192);      // [128][4][4] 8KB
    float* cst = (float*)(sm_ + 131072 + 16384);     // [4][128] 2KB

    const int tid   = threadIdx.x;
    const int tid7  = tid & 127;
    const int khalf = tid >> 7;          // 0/1: k-split
    const int hh    = tid7 & 3;
    const int bq    = tid7 >> 2;         // 0..31, handles b = bq*4..bq*4+3
    const int hidx0 = blockIdx.x * 4;

    // one-time weight load, pre-splatted
    for (int r = tid; r < 512 * 16; r += 256) {
        int k = r >> 4, idx = r & 15;
        int whh_ = idx >> 2, q = idx & 3;
        float w = whh[(size_t)(q * Hh + hidx0 + whh_) * Hh + k];
        ws2[r] = pack2(w, w);
    }
    // one-time c-state load
    if (tid < 128) {
#pragma unroll
        for (int j = 0; j < 4; j++)
            cst[hh * 128 + bq * 4 + j] = c0[(size_t)(bq * 4 + j) * Hh + hidx0 + hh];
    }
    __syncthreads();

    unsigned* barCnt   = &g_barCnt[barSel];
    unsigned* barPhase = &g_barPhase[barSel];

    const int i0 = tid, i1 = tid + 256;  // xp staging indices (b*4+q)

    for (int t = 0; t < Tt; t++) {
        const float* hp = (t & 1) ? hbuf1 : hbuf0;
        float*       hn = (t & 1) ? hbuf0 : hbuf1;

        // prefetch chunk 0 via cp.async
        {
            unsigned sa = (unsigned)__cvta_generic_to_shared(hb) + tid * 16;
            const float4* g = (const float4*)hp + tid;
#pragma unroll
            for (int i = 0; i < 8; i++)
                asm volatile("cp.async.cg.shared.global [%0], [%1], 16;"
                             :: "r"(sa + i * 4096), "l"(g + i * 256));
            asm volatile("cp.async.commit_group;" ::: "memory");
        }

        // prefetch xp tile into regs (consumed at epilogue)
        const float* xp = xp_all + (size_t)t * Bz * G4;
        float4 xr0 = *reinterpret_cast<const float4*>(
            &xp[(size_t)(i0 >> 2) * G4 + (i0 & 3) * Hh + hidx0]);
        float4 xr1 = *reinterpret_cast<const float4*>(
            &xp[(size_t)(i1 >> 2) * G4 + (i1 & 3) * Hh + hidx0]);

        u64 acc[2][4];
#pragma unroll
        for (int p = 0; p < 2; p++)
#pragma unroll
            for (int q = 0; q < 4; q++) acc[p][q] = 0ull;

        for (int c = 0; c < 8; c++) {
            if (c < 7) {
                float* nb = hb + ((c + 1) & 1) * 8192;
                unsigned sa = (unsigned)__cvta_generic_to_shared(nb) + tid * 16;
                const float4* g = (const float4*)(hp + (c + 1) * 8192) + tid;
#pragma unroll
                for (int i = 0; i < 8; i++)
                    asm volatile("cp.async.cg.shared.global [%0], [%1], 16;"
                                 :: "r"(sa + i * 4096), "l"(g + i * 256));
                asm volatile("cp.async.commit_group;" ::: "memory");
                asm volatile("cp.async.wait_group 1;" ::: "memory");
            } else {
                asm volatile("cp.async.wait_group 0;" ::: "memory");
            }
            __syncthreads();

            const float* bufk = hb + (c & 1) * 8192 + khalf * 32 * 128 + bq * 4;
            const u64* wk = ws2 + ((c * 64 + khalf * 32) * 16) + hh * 4;
#pragma unroll
            for (int kk = 0; kk < 32; kk++) {
                u64 h01 = *reinterpret_cast<const u64*>(bufk + kk * 128);
                u64 h23 = *reinterpret_cast<const u64*>(bufk + kk * 128 + 2);
                const u64* wr = wk + kk * 16;
                acc[0][0] = fma2(h01, wr[0], acc[0][0]);
                acc[1][0] = fma2(h23, wr[0], acc[1][0]);
                acc[0][1] = fma2(h01, wr[1], acc[0][1]);
                acc[1][1] = fma2(h23, wr[1], acc[1][1]);
                acc[0][2] = fma2(h01, wr[2], acc[0][2]);
                acc[1][2] = fma2(h23, wr[2], acc[1][2]);
                acc[0][3] = fma2(h01, wr[3], acc[0][3]);
                acc[1][3] = fma2(h23, wr[3], acc[1][3]);
            }
            __syncthreads();
        }

        // stage xp to smem; upper half stores partials
        *reinterpret_cast<float4*>(&xs[i0 * 4]) = xr0;
        *reinterpret_cast<float4*>(&xs[i1 * 4]) = xr1;
        if (khalf == 1) {
            u64* r = red + tid7 * 8;
#pragma unroll
            for (int p = 0; p < 2; p++)
#pragma unroll
                for (int q = 0; q < 4; q++) r[p * 4 + q] = acc[p][q];
        }
        __syncthreads();

        if (khalf == 0) {
            const u64* r = red + tid7 * 8;
            float gate[4][4];   // [q][j]
#pragma unroll
            for (int p = 0; p < 2; p++)
#pragma unroll
                for (int q = 0; q < 4; q++) {
                    u64 s = add2(acc[p][q], r[p * 4 + q]);
                    unpack2(s, gate[q][p * 2 + 0], gate[q][p * 2 + 1]);
                }
            float hv[4];
#pragma unroll
            for (int j = 0; j < 4; j++) {
                int b = bq * 4 + j;
                float gi = gate[0][j] + xs[b * 16 + 0 + hh];
                float gf = gate[1][j] + xs[b * 16 + 4 + hh];
                float gg = gate[2][j] + xs[b * 16 + 8 + hh];
                float go = gate[3][j] + xs[b * 16 + 12 + hh];
                float cc = fsig(gf) * cst[hh * 128 + b] + fsig(gi) * ftanh_(gg);
                cst[hh * 128 + b] = cc;
                hv[j] = fsig(go) * ftanh_(cc);
            }
            float4 h4 = make_float4(hv[0], hv[1], hv[2], hv[3]);
            int off = (hidx0 + hh) * 128 + bq * 4;
            *reinterpret_cast<float4*>(&hn[off]) = h4;
            *reinterpret_cast<float4*>(&hs_t[(size_t)t * Hh * Bz + off]) = h4;
        }

        // grid barrier
        __threadfence();
        __syncthreads();
        if (tid == 0) {
            unsigned target = (unsigned)(t + 1);
            unsigned a = atomicAdd(barCnt, 1u);
            if (a == NBLK - 1) {
                *barCnt = 0u;
                __threadfence();
                atomicExch(barPhase, target);
            } else {
                while (atomicAdd(barPhase, 0u) < target) __nanosleep(64);
            }
        }
        __syncthreads();
        __threadfence();
    }
}

// ---------------- encoder output transpose: out[b][h][t] = hse_t[t][h][b] ----------------
__global__ void __launch_bounds__(256)
enc_transpose(const float* __restrict__ hs_t, float* __restrict__ out) {
    __shared__ float tile[32][33];
    int t0 = blockIdx.x * 32, b0 = blockIdx.y * 32, h = blockIdx.z;
    int tx = threadIdx.x & 31, ty = threadIdx.x >> 5;
#pragma unroll
    for (int i = ty; i < 32; i += 8)
        tile[i][tx] = hs_t[(size_t)(t0 + i) * (Hh * Bz) + (size_t)h * Bz + b0 + tx];
    __syncthreads();
#pragma unroll
    for (int i = ty; i < 32; i += 8)
        out[(size_t)(b0 + i) * (Hh * Tt) + (size_t)h * Tt + t0 + tx] = tile[tx][i];
}

// ---------------- FC partial GEMM (k-split over t) ----------------
// partial[t][b][o] = sum_h hsd_t[t][h][b] * Wfc[o][h*256 + t]
__global__ void __launch_bounds__(256)
fc_partial(const float* __restrict__ hsd_t, const float* __restrict__ Wfc) {
    const int t  = blockIdx.y;
    const int o0 = blockIdx.x * 128;
    const int tid = threadIdx.x;
    const int txx = tid & 15;
    const int tyy = tid >> 4;
    const int lrow = tid >> 1;
    const int lkq  = (tid & 1) * 4;
    const int arow = tid >> 5;
    const int acol = (tid & 31) * 4;

    __shared__ __align__(16) float As[8][128];   // [h][b]
    __shared__ __align__(16) float Bs[8][128];   // [h][o]

    float acc[8][8];
#pragma unroll
    for (int i = 0; i < 8; i++)
#pragma unroll
        for (int j = 0; j < 8; j++) acc[i][j] = 0.f;

    const float* Abase = hsd_t + (size_t)t * (Hh * Bz);

    for (int h0 = 0; h0 < Hh; h0 += 8) {
        *reinterpret_cast<float4*>(&As[arow][acol]) =
            *reinterpret_cast<const float4*>(&Abase[(size_t)(h0 + arow) * Bz + acol]);
#pragma unroll
        for (int i = 0; i < 4; i++)
            Bs[lkq + i][lrow] = Wfc[(size_t)(o0 + lrow) * (Hh * Tt) + (size_t)(h0 + lkq + i) * Tt + t];
        __syncthreads();
#pragma unroll
        for (int kk = 0; kk < 8; kk++) {
            float a[8], bb[8];
            *reinterpret_cast<float4*>(&a[0]) = *reinterpret_cast<const float4*>(&As[kk][tyy * 8]);
            *reinterpret_cast<float4*>(&a[4]) = *reinterpret_cast<const float4*>(&As[kk][tyy * 8 + 4]);
            *reinterpret_cast<float4*>(&bb[0]) = *reinterpret_cast<const float4*>(&Bs[kk][txx * 8]);
            *reinterpret_cast<float4*>(&bb[4]) = *reinterpret_cast<const float4*>(&Bs[kk][txx * 8 + 4]);
#pragma unroll
            for (int i = 0; i < 8; i++)
#pragma unroll
                for (int j = 0; j < 8; j++)
                    acc[i][j] = fmaf(a[i], bb[j], acc[i][j]);
        }
        __syncthreads();
    }

    float* part = g_fcp + (size_t)t * (Bz * OUTL);
#pragma unroll
    for (int i = 0; i < 8; i++) {
        int b = tyy * 8 + i;
#pragma unroll
        for (int j = 0; j < 8; j++)
            part[(size_t)b * OUTL + o0 + txx * 8 + j] = acc[i][j];
    }
}

__global__ void fc_reduce(const float* __restrict__ bfc, float* __restrict__ decoded) {
    int i = blockIdx.x * blockDim.x + threadIdx.x;
    if (i >= Bz * OUTL) return;
    float s = bfc[i & (OUTL - 1)];
    for (int t = 0; t < Tt; t++) s += g_fcp[(size_t)t * (Bz * OUTL) + i];
    decoded[i] = s;
}

// ---------------- launch ----------------
extern "C" void kernel_launch(void* const* d_in, const int* in_sizes, int n_in,
                              void* d_out, int out_size) {
    const float* x     = (const float*)d_in[0];
    const float* h0e   = (const float*)d_in[1];
    const float* c0e   = (const float*)d_in[2];
    const float* Wih_e = (const float*)d_in[3];
    const float* Whh_e = (const float*)d_in[4];
    const float* bih_e = (const float*)d_in[5];
    const float* bhh_e = (const float*)d_in[6];
    const float* h0d   = (const float*)d_in[7];
    const float* c0d   = (const float*)d_in[8];
    const float* Wih_d = (const float*)d_in[9];
    const float* Whh_d = (const float*)d_in[10];
    const float* bih_d = (const float*)d_in[11];
    const float* bhh_d = (const float*)d_in[12];
    const float* Wfc   = (const float*)d_in[13];
    const float* bfc   = (const float*)d_in[14];

    float* out = (float*)d_out;
    float* enc_out = out;
    float* decoded = out + (size_t)Bz * Hh * Tt;

    float *xpe, *xpd, *hse, *hsd, *hA, *hB, *h2A, *h2B;
    cudaGetSymbolAddress((void**)&xpe, g_xpe);
    cudaGetSymbolAddress((void**)&xpd, g_xpd);
    cudaGetSymbolAddress((void**)&hse, g_hse);
    cudaGetSymbolAddress((void**)&hsd, g_hsd);
    cudaGetSymbolAddress((void**)&hA,  g_hA);
    cudaGetSymbolAddress((void**)&hB,  g_hB);
    cudaGetSymbolAddress((void**)&h2A, g_h2A);
    cudaGetSymbolAddress((void**)&h2B, g_h2B);

    const int SMEM = 65536 + 65536 + 8192 + 8192 + 2048;
    cudaFuncSetAttribute(lstm_persistent, cudaFuncAttributeMaxDynamicSharedMemorySize, SMEM);

    init_all<<<(Hh * Bz + 255) / 256, 256>>>(h0e, h0d);

    // encoder input projections
    inproj_gemm<0><<<dim3(16, 256), 256>>>(x, Wih_e, bih_e, bhh_e, xpe, INZ);

    // encoder recurrence (single persistent launch)
    lstm_persistent<<<NBLK, 256, SMEM>>>(xpe, Whh_e, c0e, hA, hB, hse, 0);

    // decoder input projections over hse_t
    inproj_gemm<1><<<dim3(16, 256), 256>>>(hse, Wih_d, bih_d, bhh_d, xpd, Hh);

    // decoder recurrence
    lstm_persistent<<<NBLK, 256, SMEM>>>(xpd, Whh_d, c0d, h2A, h2B, hsd, 1);

    // encoder output transpose into d_out
    enc_transpose<<<dim3(Tt / 32, Bz / 32, Hh), 256>>>(hse, enc_out);

    // final FC
    fc_partial<<<dim3(4, Tt), 256>>>(hsd, Wfc);
    fc_reduce<<<(Bz * OUTL + 255) / 256, 256>>>(bfc, decoded);
}

// round 3
// speedup vs baseline: 1.2607x; 1.0220x over previous
#include <cuda_runtime.h>
#include <math.h>

#define Bz   128
#define Hh   512
#define G4   2048
#define Tt   256
#define INZ  64
#define OUTL 512
#define NBLK 128

typedef unsigned long long u64;

// ---------------- device scratch ----------------
__device__ float g_xpe[(size_t)Tt * Bz * G4];   // [t][b][4H]
__device__ float g_xpd[(size_t)Tt * Bz * G4];
__device__ float g_hse[(size_t)Tt * Hh * Bz];   // [t][h][b]
__device__ float g_hsd[(size_t)Tt * Hh * Bz];
__device__ float g_hA[Hh * Bz];
__device__ float g_hB[Hh * Bz];
__device__ float g_h2A[Hh * Bz];
__device__ float g_h2B[Hh * Bz];
__device__ float g_fcp[(size_t)Tt * Bz * OUTL];
__device__ unsigned g_barCnt[2];
__device__ unsigned g_barPhase[2];

// ---------------- f32x2 helpers ----------------
__device__ __forceinline__ u64 pack2(float lo, float hi) {
    u64 r; asm("mov.b64 %0,{%1,%2};" : "=l"(r) : "f"(lo), "f"(hi)); return r;
}
__device__ __forceinline__ void unpack2(u64 v, float& lo, float& hi) {
    asm("mov.b64 {%0,%1},%2;" : "=f"(lo), "=f"(hi) : "l"(v));
}
__device__ __forceinline__ u64 fma2(u64 a, u64 b, u64 c) {
    u64 d; asm("fma.rn.f32x2 %0,%1,%2,%3;" : "=l"(d) : "l"(a), "l"(b), "l"(c)); return d;
}
__device__ __forceinline__ u64 add2(u64 a, u64 b) {
    u64 d; asm("add.rn.f32x2 %0,%1,%2;" : "=l"(d) : "l"(a), "l"(b)); return d;
}
__device__ __forceinline__ float fsig(float x) { return __fdividef(1.f, 1.f + __expf(-x)); }
__device__ __forceinline__ float ftanh_(float x) { return 2.f * fsig(2.f * x) - 1.f; }
__device__ __forceinline__ unsigned ld_acq(const unsigned* p) {
    unsigned v; asm volatile("ld.acquire.gpu.u32 %0,[%1];" : "=r"(v) : "l"(p) : "memory"); return v;
}

// ---------------- init ----------------
__global__ void init_all(const float* __restrict__ h0e, const float* __restrict__ h0d) {
    int i = blockIdx.x * blockDim.x + threadIdx.x;
    if (i < Hh * Bz) {
        int k = i >> 7, b = i & 127;
        g_hA[i]  = h0e[b * Hh + k];
        g_h2A[i] = h0d[b * Hh + k];
    }
    if (i < 2) { g_barCnt[i] = 0u; g_barPhase[i] = 0u; }
}

// ---------------- input projection GEMM (f32x2) ----------------
// out[(t*128+b)*2048 + n] = sum_k A[m][k]*W[n][k] + b0[n] + b1[n]
// MODE 0: A[m][k] = x[b][k][t], K=64.  MODE 1: A[m][k] = hse_t[t][k][b], K=512.
template <int MODE>
__global__ void __launch_bounds__(256)
inproj_gemm(const float* __restrict__ A_or_x, const float* __restrict__ W,
            const float* __restrict__ b0v, const float* __restrict__ b1v,
            float* __restrict__ out, int K) {
    __shared__ __align__(16) float As[8][128];
    __shared__ __align__(16) float Bs[8][128];

    const int m0  = blockIdx.y * 128;
    const int n0  = blockIdx.x * 128;
    const int tid = threadIdx.x;
    const int txx = tid & 15;
    const int tyy = tid >> 4;
    const int lrow = tid >> 1;
    const int lkq  = (tid & 1) * 4;
    const int arow = tid >> 5;
    const int acol = (tid & 31) * 4;

    u64 acc[8][4];
#pragma unroll
    for (int i = 0; i < 8; i++)
#pragma unroll
        for (int j = 0; j < 4; j++) acc[i][j] = 0ull;

    float4 aPf, bPf;
    float  aPfS[4];

    if (MODE == 1) {
        aPf = *reinterpret_cast<const float4*>(
            &A_or_x[(size_t)blockIdx.y * Hh * Bz + (size_t)arow * Bz + acol]);
    } else {
        int m = m0 + lrow;
        int tt = m >> 7, b = m & 127;
#pragma unroll
        for (int i = 0; i < 4; i++)
            aPfS[i] = A_or_x[(size_t)b * (INZ * Tt) + (size_t)(lkq + i) * Tt + tt];
    }
    bPf = *reinterpret_cast<const float4*>(&W[(size_t)(n0 + lrow) * K + lkq]);

    for (int k0 = 0; k0 < K; k0 += 8) {
        if (MODE == 1) {
            *reinterpret_cast<float4*>(&As[arow][acol]) = aPf;
        } else {
#pragma unroll
            for (int i = 0; i < 4; i++) As[lkq + i][lrow] = aPfS[i];
        }
        Bs[lkq + 0][lrow] = bPf.x; Bs[lkq + 1][lrow] = bPf.y;
        Bs[lkq + 2][lrow] = bPf.z; Bs[lkq + 3][lrow] = bPf.w;
        __syncthreads();

        int kn = k0 + 8;
        if (kn < K) {
            if (MODE == 1) {
                aPf = *reinterpret_cast<const float4*>(
                    &A_or_x[(size_t)blockIdx.y * Hh * Bz + (size_t)(kn + arow) * Bz + acol]);
            } else {
                int m = m0 + lrow;
                int tt = m >> 7, b = m & 127;
#pragma unroll
                for (int i = 0; i < 4; i++)
                    aPfS[i] = A_or_x[(size_t)b * (INZ * Tt) + (size_t)(kn + lkq + i) * Tt + tt];
            }
            bPf = *reinterpret_cast<const float4*>(&W[(size_t)(n0 + lrow) * K + kn + lkq]);
        }

#pragma unroll
        for (int kk = 0; kk < 8; kk++) {
            float a[8];
            *reinterpret_cast<float4*>(&a[0]) = *reinterpret_cast<const float4*>(&As[kk][tyy * 8]);
            *reinterpret_cast<float4*>(&a[4]) = *reinterpret_cast<const float4*>(&As[kk][tyy * 8 + 4]);
            ulonglong2 bp01 = *reinterpret_cast<const ulonglong2*>(&Bs[kk][txx * 8]);
            ulonglong2 bp23 = *reinterpret_cast<const ulonglong2*>(&Bs[kk][txx * 8 + 4]);
            u64 bp[4] = {bp01.x, bp01.y, bp23.x, bp23.y};
#pragma unroll
            for (int i = 0; i < 8; i++) {
                u64 as = pack2(a[i], a[i]);
#pragma unroll
                for (int j = 0; j < 4; j++)
                    acc[i][j] = fma2(as, bp[j], acc[i][j]);
            }
        }
        __syncthreads();
    }

#pragma unroll
    for (int i = 0; i < 8; i++) {
        int m = m0 + tyy * 8 + i;
#pragma unroll
        for (int j = 0; j < 4; j++) {
            int n = n0 + txx * 8 + 2 * j;
            float lo, hi; unpack2(acc[i][j], lo, hi);
            float2 v = make_float2(lo + b0v[n] + b1v[n], hi + b0v[n + 1] + b1v[n + 1]);
            *reinterpret_cast<float2*>(&out[(size_t)m * G4 + n]) = v;
        }
    }
}

// ---------------- persistent LSTM ----------------
// 128 blocks x 256 threads. Block owns 4 hidx x 4 gates (16 weight rows in SMEM,
// pre-splatted f32x2, loaded once). c-state in SMEM. 4 chunks of 128 k-rows,
// double-buffered cp.async. Grid barrier (acquire-poll) between steps.
__global__ void __launch_bounds__(256, 1)
lstm_persistent(const float* __restrict__ xp_all,   // [t][b][2048]
                const float* __restrict__ whh,      // [2048][512]
                const float* __restrict__ c0,       // [b][512]
                float* __restrict__ hbuf0,          // [512][128]
                float* __restrict__ hbuf1,
                float* __restrict__ hs_t,           // [t][512][128]
                int barSel) {
    extern __shared__ char sm_[];
    u64*   ws2 = (u64*)sm_;                          // [512][16] splats, 64KB
    float* hb  = (float*)(sm_ + 65536);              // [2][128][128] 128KB
    u64*   red = (u64*)(sm_ + 65536 + 131072);       // [128][8] 8KB
    float* xs  = (float*)(sm_ + 65536 + 131072 + 8192);   // [512][4] 8KB
    float* cst = (float*)(sm_ + 65536 + 131072 + 16384);  // [4][128] 2KB

    const int tid   = threadIdx.x;
    const int tid7  = tid & 127;
    const int khalf = tid >> 7;
    const int hh    = tid7 & 3;
    const int bq    = tid7 >> 2;
    const int hidx0 = blockIdx.x * 4;

    for (int r = tid; r < 512 * 16; r += 256) {
        int k = r >> 4, idx = r & 15;
        int wh = idx >> 2, q = idx & 3;
        float w = whh[(size_t)(q * Hh + hidx0 + wh) * Hh + k];
        ws2[r] = pack2(w, w);
    }
    if (tid < 128) {
#pragma unroll
        for (int j = 0; j < 4; j++)
            cst[hh * 128 + bq * 4 + j] = c0[(size_t)(bq * 4 + j) * Hh + hidx0 + hh];
    }
    __syncthreads();

    unsigned* barCnt   = &g_barCnt[barSel];
    unsigned* barPhase = &g_barPhase[barSel];

    const int i0 = tid, i1 = tid + 256;
    const unsigned hb_s = (unsigned)__cvta_generic_to_shared(hb);

    for (int t = 0; t < Tt; t++) {
        const float* hp = (t & 1) ? hbuf1 : hbuf0;
        float*       hn = (t & 1) ? hbuf0 : hbuf1;

        // issue chunks 0,1 (64KB each)
#pragma unroll
        for (int c = 0; c < 2; c++) {
            unsigned sa = hb_s + c * 65536 + tid * 16;
            const char* g = (const char*)(hp + c * 16384) + tid * 16;
#pragma unroll
            for (int i = 0; i < 16; i++)
                asm volatile("cp.async.cg.shared.global [%0], [%1], 16;"
                             :: "r"(sa + i * 4096), "l"(g + i * 4096));
            asm volatile("cp.async.commit_group;" ::: "memory");
        }

        const float* xp = xp_all + (size_t)t * Bz * G4;
        float4 xr0 = *reinterpret_cast<const float4*>(
            &xp[(size_t)(i0 >> 2) * G4 + (i0 & 3) * Hh + hidx0]);
        float4 xr1 = *reinterpret_cast<const float4*>(
            &xp[(size_t)(i1 >> 2) * G4 + (i1 & 3) * Hh + hidx0]);

        u64 acc[2][4];
#pragma unroll
        for (int p = 0; p < 2; p++)
#pragma unroll
            for (int q = 0; q < 4; q++) acc[p][q] = 0ull;

#pragma unroll
        for (int c = 0; c < 4; c++) {
            if (c < 3) asm volatile("cp.async.wait_group 1;" ::: "memory");
            else       asm volatile("cp.async.wait_group 0;" ::: "memory");
            __syncthreads();

            const float* bufk = hb + (c & 1) * 16384 + khalf * 64 * 128 + bq * 4;
            const u64*   wk   = ws2 + (size_t)(c * 128 + khalf * 64) * 16 + hh * 4;
#pragma unroll 16
            for (int kk = 0; kk < 64; kk++) {
                ulonglong2 hpair = *reinterpret_cast<const ulonglong2*>(bufk + (size_t)kk * 128);
                ulonglong2 w01 = *reinterpret_cast<const ulonglong2*>(wk + (size_t)kk * 16);
                ulonglong2 w23 = *reinterpret_cast<const ulonglong2*>(wk + (size_t)kk * 16 + 2);
                acc[0][0] = fma2(hpair.x, w01.x, acc[0][0]);
                acc[1][0] = fma2(hpair.y, w01.x, acc[1][0]);
                acc[0][1] = fma2(hpair.x, w01.y, acc[0][1]);
                acc[1][1] = fma2(hpair.y, w01.y, acc[1][1]);
                acc[0][2] = fma2(hpair.x, w23.x, acc[0][2]);
                acc[1][2] = fma2(hpair.y, w23.x, acc[1][2]);
                acc[0][3] = fma2(hpair.x, w23.y, acc[0][3]);
                acc[1][3] = fma2(hpair.y, w23.y, acc[1][3]);
            }

            if (c < 2) {
                __syncthreads();
                unsigned sa = hb_s + (c & 1) * 65536 + tid * 16;
                const char* g = (const char*)(hp + (c + 2) * 16384) + tid * 16;
#pragma unroll
                for (int i = 0; i < 16; i++)
                    asm volatile("cp.async.cg.shared.global [%0], [%1], 16;"
                                 :: "r"(sa + i * 4096), "l"(g + i * 4096));
                asm volatile("cp.async.commit_group;" ::: "memory");
            }
        }

        // stage xp + partials
        *reinterpret_cast<float4*>(&xs[i0 * 4]) = xr0;
        *reinterpret_cast<float4*>(&xs[i1 * 4]) = xr1;
        if (khalf == 1) {
            u64* r = red + tid7 * 8;
#pragma unroll
            for (int p = 0; p < 2; p++)
#pragma unroll
                for (int q = 0; q < 4; q++) r[p * 4 + q] = acc[p][q];
        }
        __syncthreads();

        if (khalf == 0) {
            const u64* r = red + tid7 * 8;
            float gate[4][4];
#pragma unroll
            for (int p = 0; p < 2; p++)
#pragma unroll
                for (int q = 0; q < 4; q++) {
                    u64 s = add2(acc[p][q], r[p * 4 + q]);
                    unpack2(s, gate[q][p * 2 + 0], gate[q][p * 2 + 1]);
                }
            float hv[4];
#pragma unroll
            for (int j = 0; j < 4; j++) {
                int b = bq * 4 + j;
                float gi = gate[0][j] + xs[b * 16 + 0 + hh];
                float gf = gate[1][j] + xs[b * 16 + 4 + hh];
                float gg = gate[2][j] + xs[b * 16 + 8 + hh];
                float go = gate[3][j] + xs[b * 16 + 12 + hh];
                float cc = fsig(gf) * cst[hh * 128 + b] + fsig(gi) * ftanh_(gg);
                cst[hh * 128 + b] = cc;
                hv[j] = fsig(go) * ftanh_(cc);
            }
            float4 h4 = make_float4(hv[0], hv[1], hv[2], hv[3]);
            int off = (hidx0 + hh) * 128 + bq * 4;
            *reinterpret_cast<float4*>(&hn[off]) = h4;
            *reinterpret_cast<float4*>(&hs_t[(size_t)t * Hh * Bz + off]) = h4;
        }

        // grid barrier (release via fence+exch, acquire poll)
        __threadfence();
        __syncthreads();
        if (tid == 0) {
            unsigned target = (unsigned)(t + 1);
            unsigned a = atomicAdd(barCnt, 1u);
            if (a == NBLK - 1) {
                *barCnt = 0u;
                __threadfence();
                atomicExch(barPhase, target);
            } else {
                while (ld_acq(barPhase) < target) {}
            }
        }
        __syncthreads();
    }
}

// ---------------- encoder output transpose: out[b][h][t] = hse_t[t][h][b] ----------------
__global__ void __launch_bounds__(256)
enc_transpose(const float* __restrict__ hs_t, float* __restrict__ out) {
    __shared__ float tile[32][33];
    int t0 = blockIdx.x * 32, b0 = blockIdx.y * 32, h = blockIdx.z;
    int tx = threadIdx.x & 31, ty = threadIdx.x >> 5;
#pragma unroll
    for (int i = ty; i < 32; i += 8)
        tile[i][tx] = hs_t[(size_t)(t0 + i) * (Hh * Bz) + (size_t)h * Bz + b0 + tx];
    __syncthreads();
#pragma unroll
    for (int i = ty; i < 32; i += 8)
        out[(size_t)(b0 + i) * (Hh * Tt) + (size_t)h * Tt + t0 + tx] = tile[tx][i];
}

// ---------------- FC partial GEMM (f32x2, k-split over t) ----------------
__global__ void __launch_bounds__(256)
fc_partial(const float* __restrict__ hsd_t, const float* __restrict__ Wfc) {
    const int t  = blockIdx.y;
    const int o0 = blockIdx.x * 128;
    const int tid = threadIdx.x;
    const int txx = tid & 15;
    const int tyy = tid >> 4;
    const int lrow = tid >> 1;
    const int lkq  = (tid & 1) * 4;
    const int arow = tid >> 5;
    const int acol = (tid & 31) * 4;

    __shared__ __align__(16) float As[8][128];   // [h][b]
    __shared__ __align__(16) float Bs[8][128];   // [h][o]

    u64 acc[8][4];
#pragma unroll
    for (int i = 0; i < 8; i++)
#pragma unroll
        for (int j = 0; j < 4; j++) acc[i][j] = 0ull;

    const float* Abase = hsd_t + (size_t)t * (Hh * Bz);

    for (int h0 = 0; h0 < Hh; h0 += 8) {
        *reinterpret_cast<float4*>(&As[arow][acol]) =
            *reinterpret_cast<const float4*>(&Abase[(size_t)(h0 + arow) * Bz + acol]);
#pragma unroll
        for (int i = 0; i < 4; i++)
            Bs[lkq + i][lrow] = Wfc[(size_t)(o0 + lrow) * (Hh * Tt) + (size_t)(h0 + lkq + i) * Tt + t];
        __syncthreads();
#pragma unroll
        for (int kk = 0; kk < 8; kk++) {
            float a[8];
            *reinterpret_cast<float4*>(&a[0]) = *reinterpret_cast<const float4*>(&As[kk][tyy * 8]);
            *reinterpret_cast<float4*>(&a[4]) = *reinterpret_cast<const float4*>(&As[kk][tyy * 8 + 4]);
            ulonglong2 bp01 = *reinterpret_cast<const ulonglong2*>(&Bs[kk][txx * 8]);
            ulonglong2 bp23 = *reinterpret_cast<const ulonglong2*>(&Bs[kk][txx * 8 + 4]);
            u64 bp[4] = {bp01.x, bp01.y, bp23.x, bp23.y};
#pragma unroll
            for (int i = 0; i < 8; i++) {
                u64 as = pack2(a[i], a[i]);
#pragma unroll
                for (int j = 0; j < 4; j++)
                    acc[i][j] = fma2(as, bp[j], acc[i][j]);
            }
        }
        __syncthreads();
    }

    float* part = g_fcp + (size_t)t * (Bz * OUTL);
#pragma unroll
    for (int i = 0; i < 8; i++) {
        int b = tyy * 8 + i;
#pragma unroll
        for (int j = 0; j < 4; j++) {
            float lo, hi; unpack2(acc[i][j], lo, hi);
            *reinterpret_cast<float2*>(&part[(size_t)b * OUTL + o0 + txx * 8 + 2 * j]) =
                make_float2(lo, hi);
        }
    }
}

__global__ void fc_reduce(const float* __restrict__ bfc, float* __restrict__ decoded) {
    int i = blockIdx.x * blockDim.x + threadIdx.x;
    if (i >= Bz * OUTL) return;
    float s = bfc[i & (OUTL - 1)];
    for (int t = 0; t < Tt; t++) s += g_fcp[(size_t)t * (Bz * OUTL) + i];
    decoded[i] = s;
}

// ---------------- launch ----------------
extern "C" void kernel_launch(void* const* d_in, const int* in_sizes, int n_in,
                              void* d_out, int out_size) {
    const float* x     = (const float*)d_in[0];
    const float* h0e   = (const float*)d_in[1];
    const float* c0e   = (const float*)d_in[2];
    const float* Wih_e = (const float*)d_in[3];
    const float* Whh_e = (const float*)d_in[4];
    const float* bih_e = (const float*)d_in[5];
    const float* bhh_e = (const float*)d_in[6];
    const float* h0d   = (const float*)d_in[7];
    const float* c0d   = (const float*)d_in[8];
    const float* Wih_d = (const float*)d_in[9];
    const float* Whh_d = (const float*)d_in[10];
    const float* bih_d = (const float*)d_in[11];
    const float* bhh_d = (const float*)d_in[12];
    const float* Wfc   = (const float*)d_in[13];
    const float* bfc   = (const float*)d_in[14];

    float* out = (float*)d_out;
    float* enc_out = out;
    float* decoded = out + (size_t)Bz * Hh * Tt;

    float *xpe, *xpd, *hse, *hsd, *hA, *hB, *h2A, *h2B;
    cudaGetSymbolAddress((void**)&xpe, g_xpe);
    cudaGetSymbolAddress((void**)&xpd, g_xpd);
    cudaGetSymbolAddress((void**)&hse, g_hse);
    cudaGetSymbolAddress((void**)&hsd, g_hsd);
    cudaGetSymbolAddress((void**)&hA,  g_hA);
    cudaGetSymbolAddress((void**)&hB,  g_hB);
    cudaGetSymbolAddress((void**)&h2A, g_h2A);
    cudaGetSymbolAddress((void**)&h2B, g_h2B);

    const int SMEM = 65536 + 131072 + 8192 + 8192 + 2048;
    cudaFuncSetAttribute(lstm_persistent, cudaFuncAttributeMaxDynamicSharedMemorySize, SMEM);

    init_all<<<(Hh * Bz + 255) / 256, 256>>>(h0e, h0d);

    inproj_gemm<0><<<dim3(16, 256), 256>>>(x, Wih_e, bih_e, bhh_e, xpe, INZ);

    lstm_persistent<<<NBLK, 256, SMEM>>>(xpe, Whh_e, c0e, hA, hB, hse, 0);

    inproj_gemm<1><<<dim3(16, 256), 256>>>(hse, Wih_d, bih_d, bhh_d, xpd, Hh);

    lstm_persistent<<<NBLK, 256, SMEM>>>(xpd, Whh_d, c0d, h2A, h2B, hsd, 1);

    enc_transpose<<<dim3(Tt / 32, Bz / 32, Hh), 256>>>(hse, enc_out);

    fc_partial<<<dim3(4, Tt), 256>>>(hsd, Wfc);
    fc_reduce<<<(Bz * OUTL + 255) / 256, 256>>>(bfc, decoded);
}

// round 4
// speedup vs baseline: 1.2810x; 1.0161x over previous
#include <cuda_runtime.h>
#include <math.h>

#define Bz   128
#define Hh   512
#define G4   2048
#define Tt   256
#define INZ  64
#define OUTL 512
#define NBLK 128

typedef unsigned long long u64;

// ---------------- device scratch ----------------
__device__ float g_xpe[(size_t)Tt * Bz * G4];   // [t][b][4H]
__device__ float g_xpd[(size_t)Tt * Bz * G4];
__device__ float g_hse[(size_t)Tt * Hh * Bz];   // [t][h][b]
__device__ float g_hsd[(size_t)Tt * Hh * Bz];
__device__ float g_hA[Hh * Bz];
__device__ float g_hB[Hh * Bz];
__device__ float g_h2A[Hh * Bz];
__device__ float g_h2B[Hh * Bz];
__device__ float g_fcp[(size_t)Tt * Bz * OUTL];
__device__ unsigned g_barCnt[2];

// ---------------- f32x2 helpers ----------------
__device__ __forceinline__ u64 pack2(float lo, float hi) {
    u64 r; asm("mov.b64 %0,{%1,%2};" : "=l"(r) : "f"(lo), "f"(hi)); return r;
}
__device__ __forceinline__ void unpack2(u64 v, float& lo, float& hi) {
    asm("mov.b64 {%0,%1},%2;" : "=f"(lo), "=f"(hi) : "l"(v));
}
__device__ __forceinline__ u64 fma2(u64 a, u64 b, u64 c) {
    u64 d; asm("fma.rn.f32x2 %0,%1,%2,%3;" : "=l"(d) : "l"(a), "l"(b), "l"(c)); return d;
}
__device__ __forceinline__ u64 add2(u64 a, u64 b) {
    u64 d; asm("add.rn.f32x2 %0,%1,%2;" : "=l"(d) : "l"(a), "l"(b)); return d;
}
__device__ __forceinline__ float fsig(float x) { return __fdividef(1.f, 1.f + __expf(-x)); }
__device__ __forceinline__ float ftanh_(float x) { return 2.f * fsig(2.f * x) - 1.f; }
__device__ __forceinline__ unsigned ld_acq(const unsigned* p) {
    unsigned v; asm volatile("ld.acquire.gpu.u32 %0,[%1];" : "=r"(v) : "l"(p) : "memory"); return v;
}
__device__ __forceinline__ void red_rel_add(unsigned* p, unsigned v) {
    asm volatile("red.release.gpu.global.add.u32 [%0],%1;" :: "l"(p), "r"(v) : "memory");
}

// ---------------- init ----------------
__global__ void init_h(const float* __restrict__ h0e, const float* __restrict__ h0d) {
    int i = blockIdx.x * blockDim.x + threadIdx.x;
    if (i < Hh * Bz) {
        int k = i >> 7, b = i & 127;
        g_hA[i]  = h0e[b * Hh + k];
        g_h2A[i] = h0d[b * Hh + k];
    }
}
__global__ void init_bar() {
    if (threadIdx.x < 2) g_barCnt[threadIdx.x] = 0u;
}

// ---------------- input projection GEMM (f32x2) ----------------
template <int MODE>
__global__ void __launch_bounds__(256)
inproj_gemm(const float* __restrict__ A_or_x, const float* __restrict__ W,
            const float* __restrict__ b0v, const float* __restrict__ b1v,
            float* __restrict__ out, int K) {
    __shared__ __align__(16) float As[8][128];
    __shared__ __align__(16) float Bs[8][128];

    const int m0  = blockIdx.y * 128;
    const int n0  = blockIdx.x * 128;
    const int tid = threadIdx.x;
    const int txx = tid & 15;
    const int tyy = tid >> 4;
    const int lrow = tid >> 1;
    const int lkq  = (tid & 1) * 4;
    const int arow = tid >> 5;
    const int acol = (tid & 31) * 4;

    u64 acc[8][4];
#pragma unroll
    for (int i = 0; i < 8; i++)
#pragma unroll
        for (int j = 0; j < 4; j++) acc[i][j] = 0ull;

    float4 aPf, bPf;
    float  aPfS[4];

    if (MODE == 1) {
        aPf = *reinterpret_cast<const float4*>(
            &A_or_x[(size_t)blockIdx.y * Hh * Bz + (size_t)arow * Bz + acol]);
    } else {
        int m = m0 + lrow;
        int tt = m >> 7, b = m & 127;
#pragma unroll
        for (int i = 0; i < 4; i++)
            aPfS[i] = A_or_x[(size_t)b * (INZ * Tt) + (size_t)(lkq + i) * Tt + tt];
    }
    bPf = *reinterpret_cast<const float4*>(&W[(size_t)(n0 + lrow) * K + lkq]);

    for (int k0 = 0; k0 < K; k0 += 8) {
        if (MODE == 1) {
            *reinterpret_cast<float4*>(&As[arow][acol]) = aPf;
        } else {
#pragma unroll
            for (int i = 0; i < 4; i++) As[lkq + i][lrow] = aPfS[i];
        }
        Bs[lkq + 0][lrow] = bPf.x; Bs[lkq + 1][lrow] = bPf.y;
        Bs[lkq + 2][lrow] = bPf.z; Bs[lkq + 3][lrow] = bPf.w;
        __syncthreads();

        int kn = k0 + 8;
        if (kn < K) {
            if (MODE == 1) {
                aPf = *reinterpret_cast<const float4*>(
                    &A_or_x[(size_t)blockIdx.y * Hh * Bz + (size_t)(kn + arow) * Bz + acol]);
            } else {
                int m = m0 + lrow;
                int tt = m >> 7, b = m & 127;
#pragma unroll
                for (int i = 0; i < 4; i++)
                    aPfS[i] = A_or_x[(size_t)b * (INZ * Tt) + (size_t)(kn + lkq + i) * Tt + tt];
            }
            bPf = *reinterpret_cast<const float4*>(&W[(size_t)(n0 + lrow) * K + kn + lkq]);
        }

#pragma unroll
        for (int kk = 0; kk < 8; kk++) {
            float a[8];
            *reinterpret_cast<float4*>(&a[0]) = *reinterpret_cast<const float4*>(&As[kk][tyy * 8]);
            *reinterpret_cast<float4*>(&a[4]) = *reinterpret_cast<const float4*>(&As[kk][tyy * 8 + 4]);
            ulonglong2 bp01 = *reinterpret_cast<const ulonglong2*>(&Bs[kk][txx * 8]);
            ulonglong2 bp23 = *reinterpret_cast<const ulonglong2*>(&Bs[kk][txx * 8 + 4]);
            u64 bp[4] = {bp01.x, bp01.y, bp23.x, bp23.y};
#pragma unroll
            for (int i = 0; i < 8; i++) {
                u64 as = pack2(a[i], a[i]);
#pragma unroll
                for (int j = 0; j < 4; j++)
                    acc[i][j] = fma2(as, bp[j], acc[i][j]);
            }
        }
        __syncthreads();
    }

#pragma unroll
    for (int i = 0; i < 8; i++) {
        int m = m0 + tyy * 8 + i;
#pragma unroll
        for (int j = 0; j < 4; j++) {
            int n = n0 + txx * 8 + 2 * j;
            float lo, hi; unpack2(acc[i][j], lo, hi);
            float2 v = make_float2(lo + b0v[n] + b1v[n], hi + b0v[n + 1] + b1v[n + 1]);
            *reinterpret_cast<float2*>(&out[(size_t)m * G4 + n]) = v;
        }
    }
}

// ---------------- persistent LSTM ----------------
// 128 blocks x 512 threads. Block owns 4 hidx x 4 gates (16 weight rows,
// pre-splatted f32x2 in SMEM). 4 k-groups of 128 threads each cover 32 k-rows
// per chunk; 4 chunks of 128 k-rows, double-buffered cp.async, 1 sync/chunk.
// Monotonic red.release grid barrier between steps.
__global__ void __launch_bounds__(512, 1)
lstm_persistent(const float* __restrict__ xp_all,   // [t][b][2048]
                const float* __restrict__ whh,      // [2048][512]
                const float* __restrict__ c0,       // [b][512]
                float* __restrict__ hbuf0,          // [512][128]
                float* __restrict__ hbuf1,
                float* __restrict__ hs_t,           // [t][512][128]
                int barSel) {
    extern __shared__ char sm_[];
    u64*   ws2 = (u64*)sm_;                               // [512][16] splats, 64KB
    float* hb  = (float*)(sm_ + 65536);                   // [2][128][128] 128KB
    u64*   red = (u64*)(sm_ + 65536 + 131072);            // [3][128][8] 24KB
    float* xs  = (float*)(sm_ + 65536 + 131072 + 24576);  // [512][4] 8KB
    float* cst = (float*)(sm_ + 65536 + 131072 + 24576 + 8192);  // [4][128] 2KB

    const int tid   = threadIdx.x;
    const int g     = tid >> 7;          // k-group 0..3
    const int tid7  = tid & 127;
    const int hh    = tid7 & 3;
    const int bq    = tid7 >> 2;
    const int hidx0 = blockIdx.x * 4;

    // one-time weight load, pre-splatted: ws2[k][wh*4+q] = (w,w)
    for (int r = tid; r < 512 * 16; r += 512) {
        int k = r >> 4, idx = r & 15;
        int wh = idx >> 2, q = idx & 3;
        float w = whh[(size_t)(q * Hh + hidx0 + wh) * Hh + k];
        ws2[r] = pack2(w, w);
    }
    if (tid < 128) {
#pragma unroll
        for (int j = 0; j < 4; j++)
            cst[hh * 128 + bq * 4 + j] = c0[(size_t)(bq * 4 + j) * Hh + hidx0 + hh];
    }
    __syncthreads();

    unsigned* barCnt = &g_barCnt[barSel];
    const unsigned hb_s = (unsigned)__cvta_generic_to_shared(hb);

    // prefetch xp for t=0 (xs index = tid = b*4+q, holds hidx0..hidx0+3)
    float4 xr = *reinterpret_cast<const float4*>(
        &xp_all[(size_t)(tid >> 2) * G4 + (tid & 3) * Hh + hidx0]);

    for (int t = 0; t < Tt; t++) {
        const float* hp = (t & 1) ? hbuf1 : hbuf0;
        float*       hn = (t & 1) ? hbuf0 : hbuf1;

        // issue chunk 0 (64KB; 8 x 16B per thread)
        {
            unsigned sa = hb_s + tid * 16;
            const char* gp = (const char*)hp + tid * 16;
#pragma unroll
            for (int i = 0; i < 8; i++)
                asm volatile("cp.async.cg.shared.global [%0], [%1], 16;"
                             :: "r"(sa + i * 8192), "l"(gp + i * 8192));
            asm volatile("cp.async.commit_group;" ::: "memory");
        }

        u64 acc[8];
#pragma unroll
        for (int j = 0; j < 8; j++) acc[j] = 0ull;

#pragma unroll
        for (int c = 0; c < 4; c++) {
            asm volatile("cp.async.wait_group 0;" ::: "memory");
            __syncthreads();

            if (c < 3) {
                unsigned sa = hb_s + ((c + 1) & 1) * 65536 + tid * 16;
                const char* gp = (const char*)(hp + (c + 1) * 16384) + tid * 16;
#pragma unroll
                for (int i = 0; i < 8; i++)
                    asm volatile("cp.async.cg.shared.global [%0], [%1], 16;"
                                 :: "r"(sa + i * 8192), "l"(gp + i * 8192));
                asm volatile("cp.async.commit_group;" ::: "memory");
            }

            const float* bufk = hb + (c & 1) * 16384 + (size_t)(g * 32) * 128 + bq * 4;
            const u64*   wk   = ws2 + (size_t)(c * 128 + g * 32) * 16 + hh * 4;
#pragma unroll 8
            for (int kk = 0; kk < 32; kk++) {
                ulonglong2 hpair = *reinterpret_cast<const ulonglong2*>(bufk + (size_t)kk * 128);
                ulonglong2 w01 = *reinterpret_cast<const ulonglong2*>(wk + (size_t)kk * 16);
                ulonglong2 w23 = *reinterpret_cast<const ulonglong2*>(wk + (size_t)kk * 16 + 2);
                acc[0] = fma2(hpair.x, w01.x, acc[0]);
                acc[4] = fma2(hpair.y, w01.x, acc[4]);
                acc[1] = fma2(hpair.x, w01.y, acc[1]);
                acc[5] = fma2(hpair.y, w01.y, acc[5]);
                acc[2] = fma2(hpair.x, w23.x, acc[2]);
                acc[6] = fma2(hpair.y, w23.x, acc[6]);
                acc[3] = fma2(hpair.x, w23.y, acc[3]);
                acc[7] = fma2(hpair.y, w23.y, acc[7]);
            }
        }

        // stage xp + partials
        *reinterpret_cast<float4*>(&xs[tid * 4]) = xr;
        if (g != 0) {
            u64* r = red + (size_t)(g - 1) * 1024 + tid7 * 8;
#pragma unroll
            for (int j = 0; j < 8; j++) r[j] = acc[j];
        }
        __syncthreads();

        if (g == 0) {
            float gate[4][4];   // [q][j]  j = b within group of 4
#pragma unroll
            for (int p = 0; p < 2; p++)
#pragma unroll
                for (int q = 0; q < 4; q++) {
                    u64 s = acc[p * 4 + q];
                    s = add2(s, red[0 * 1024 + tid7 * 8 + p * 4 + q]);
                    s = add2(s, red[1 * 1024 + tid7 * 8 + p * 4 + q]);
                    s = add2(s, red[2 * 1024 + tid7 * 8 + p * 4 + q]);
                    unpack2(s, gate[q][p * 2 + 0], gate[q][p * 2 + 1]);
                }
            float hv[4];
#pragma unroll
            for (int j = 0; j < 4; j++) {
                int b = bq * 4 + j;
                float gi = gate[0][j] + xs[b * 16 + 0 + hh];
                float gf = gate[1][j] + xs[b * 16 + 4 + hh];
                float gg = gate[2][j] + xs[b * 16 + 8 + hh];
                float go = gate[3][j] + xs[b * 16 + 12 + hh];
                float cc = fsig(gf) * cst[hh * 128 + b] + fsig(gi) * ftanh_(gg);
                cst[hh * 128 + b] = cc;
                hv[j] = fsig(go) * ftanh_(cc);
            }
            float4 h4 = make_float4(hv[0], hv[1], hv[2], hv[3]);
            int off = (hidx0 + hh) * 128 + bq * 4;
            *reinterpret_cast<float4*>(&hn[off]) = h4;
            *reinterpret_cast<float4*>(&hs_t[(size_t)t * Hh * Bz + off]) = h4;
        }

        // prefetch next step's xp (independent of h) before the barrier
        if (t + 1 < Tt)
            xr = *reinterpret_cast<const float4*>(
                &xp_all[(size_t)(t + 1) * Bz * G4 +
                        (size_t)(tid >> 2) * G4 + (tid & 3) * Hh + hidx0]);

        if (t + 1 < Tt) {
            __threadfence();
            __syncthreads();
            if (tid == 0) {
                red_rel_add(barCnt, 1u);
                unsigned target = (unsigned)(NBLK * (t + 1));
                while (ld_acq(barCnt) < target) {}
            }
            __syncthreads();
        }
    }
}

// ---------------- encoder output transpose: out[b][h][t] = hse_t[t][h][b] ----------------
__global__ void __launch_bounds__(256)
enc_transpose(const float* __restrict__ hs_t, float* __restrict__ out) {
    __shared__ float tile[32][33];
    int t0 = blockIdx.x * 32, b0 = blockIdx.y * 32, h = blockIdx.z;
    int tx = threadIdx.x & 31, ty = threadIdx.x >> 5;
#pragma unroll
    for (int i = ty; i < 32; i += 8)
        tile[i][tx] = hs_t[(size_t)(t0 + i) * (Hh * Bz) + (size_t)h * Bz + b0 + tx];
    __syncthreads();
#pragma unroll
    for (int i = ty; i < 32; i += 8)
        out[(size_t)(b0 + i) * (Hh * Tt) + (size_t)h * Tt + t0 + tx] = tile[tx][i];
}

// ---------------- FC partial GEMM (f32x2, k-split over t) ----------------
__global__ void __launch_bounds__(256)
fc_partial(const float* __restrict__ hsd_t, const float* __restrict__ Wfc) {
    const int t  = blockIdx.y;
    const int o0 = blockIdx.x * 128;
    const int tid = threadIdx.x;
    const int txx = tid & 15;
    const int tyy = tid >> 4;
    const int lrow = tid >> 1;
    const int lkq  = (tid & 1) * 4;
    const int arow = tid >> 5;
    const int acol = (tid & 31) * 4;

    __shared__ __align__(16) float As[8][128];
    __shared__ __align__(16) float Bs[8][128];

    u64 acc[8][4];
#pragma unroll
    for (int i = 0; i < 8; i++)
#pragma unroll
        for (int j = 0; j < 4; j++) acc[i][j] = 0ull;

    const float* Abase = hsd_t + (size_t)t * (Hh * Bz);

    for (int h0 = 0; h0 < Hh; h0 += 8) {
        *reinterpret_cast<float4*>(&As[arow][acol]) =
            *reinterpret_cast<const float4*>(&Abase[(size_t)(h0 + arow) * Bz + acol]);
#pragma unroll
        for (int i = 0; i < 4; i++)
            Bs[lkq + i][lrow] = Wfc[(size_t)(o0 + lrow) * (Hh * Tt) + (size_t)(h0 + lkq + i) * Tt + t];
        __syncthreads();
#pragma unroll
        for (int kk = 0; kk < 8; kk++) {
            float a[8];
            *reinterpret_cast<float4*>(&a[0]) = *reinterpret_cast<const float4*>(&As[kk][tyy * 8]);
            *reinterpret_cast<float4*>(&a[4]) = *reinterpret_cast<const float4*>(&As[kk][tyy * 8 + 4]);
            ulonglong2 bp01 = *reinterpret_cast<const ulonglong2*>(&Bs[kk][txx * 8]);
            ulonglong2 bp23 = *reinterpret_cast<const ulonglong2*>(&Bs[kk][txx * 8 + 4]);
            u64 bp[4] = {bp01.x, bp01.y, bp23.x, bp23.y};
#pragma unroll
            for (int i = 0; i < 8; i++) {
                u64 as = pack2(a[i], a[i]);
#pragma unroll
                for (int j = 0; j < 4; j++)
                    acc[i][j] = fma2(as, bp[j], acc[i][j]);
            }
        }
        __syncthreads();
    }

    float* part = g_fcp + (size_t)t * (Bz * OUTL);
#pragma unroll
    for (int i = 0; i < 8; i++) {
        int b = tyy * 8 + i;
#pragma unroll
        for (int j = 0; j < 4; j++) {
            float lo, hi; unpack2(acc[i][j], lo, hi);
            *reinterpret_cast<float2*>(&part[(size_t)b * OUTL + o0 + txx * 8 + 2 * j]) =
                make_float2(lo, hi);
        }
    }
}

__global__ void fc_reduce(const float* __restrict__ bfc, float* __restrict__ decoded) {
    int i = blockIdx.x * blockDim.x + threadIdx.x;
    if (i >= Bz * OUTL) return;
    float s = bfc[i & (OUTL - 1)];
    for (int t = 0; t < Tt; t++) s += g_fcp[(size_t)t * (Bz * OUTL) + i];
    decoded[i] = s;
}

// ---------------- launch ----------------
extern "C" void kernel_launch(void* const* d_in, const int* in_sizes, int n_in,
                              void* d_out, int out_size) {
    const float* x     = (const float*)d_in[0];
    const float* h0e   = (const float*)d_in[1];
    const float* c0e   = (const float*)d_in[2];
    const float* Wih_e = (const float*)d_in[3];
    const float* Whh_e = (const float*)d_in[4];
    const float* bih_e = (const float*)d_in[5];
    const float* bhh_e = (const float*)d_in[6];
    const float* h0d   = (const float*)d_in[7];
    const float* c0d   = (const float*)d_in[8];
    const float* Wih_d = (const float*)d_in[9];
    const float* Whh_d = (const float*)d_in[10];
    const float* bih_d = (const float*)d_in[11];
    const float* bhh_d = (const float*)d_in[12];
    const float* Wfc   = (const float*)d_in[13];
    const float* bfc   = (const float*)d_in[14];

    float* out = (float*)d_out;
    float* enc_out = out;
    float* decoded = out + (size_t)Bz * Hh * Tt;

    float *xpe, *xpd, *hse, *hsd, *hA, *hB, *h2A, *h2B;
    cudaGetSymbolAddress((void**)&xpe, g_xpe);
    cudaGetSymbolAddress((void**)&xpd, g_xpd);
    cudaGetSymbolAddress((void**)&hse, g_hse);
    cudaGetSymbolAddress((void**)&hsd, g_hsd);
    cudaGetSymbolAddress((void**)&hA,  g_hA);
    cudaGetSymbolAddress((void**)&hB,  g_hB);
    cudaGetSymbolAddress((void**)&h2A, g_h2A);
    cudaGetSymbolAddress((void**)&h2B, g_h2B);

    const int SMEM = 65536 + 131072 + 24576 + 8192 + 2048;   // 231424
    cudaFuncSetAttribute(lstm_persistent, cudaFuncAttributeMaxDynamicSharedMemorySize, SMEM);

    init_h<<<(Hh * Bz + 255) / 256, 256>>>(h0e, h0d);
    init_bar<<<1, 32>>>();

    inproj_gemm<0><<<dim3(16, 256), 256>>>(x, Wih_e, bih_e, bhh_e, xpe, INZ);

    lstm_persistent<<<NBLK, 512, SMEM>>>(xpe, Whh_e, c0e, hA, hB, hse, 0);

    inproj_gemm<1><<<dim3(16, 256), 256>>>(hse, Wih_d, bih_d, bhh_d, xpd, Hh);

    lstm_persistent<<<NBLK, 512, SMEM>>>(xpd, Whh_d, c0d, h2A, h2B, hsd, 1);

    enc_transpose<<<dim3(Tt / 32, Bz / 32, Hh), 256>>>(hse, enc_out);

    fc_partial<<<dim3(4, Tt), 256>>>(hsd, Wfc);
    fc_reduce<<<(Bz * OUTL + 255) / 256, 256>>>(bfc, decoded);
}